// round 16
// baseline (speedup 1.0000x reference)
#include <cuda_runtime.h>
#include <math.h>

// Problem constants
#define BB 4
#define NN 2048
#define DIM 512
#define HEADS 8
#define DH 64
#define HIDDEN 512          // HEADS*DH
#define THC 1536            // 3*HIDDEN

// ---------------- scratch (device globals: allocation-free rule) ----------
__device__ float    g_qkv[(size_t)BB * NN * THC];          // 48 MB
__device__ float    g_q  [(size_t)BB * HEADS * NN * DH];   // 16 MB
// fragment-major packed operands (tf32 bit patterns)
__device__ unsigned g_kp  [(size_t)BB * HEADS * NN * DH];  // 16 MB  K packed
__device__ unsigned g_vp  [(size_t)BB * HEADS * NN * DH];  // 16 MB  V packed
__device__ unsigned g_xp  [(size_t)BB * NN * DIM];         // 16 MB  x packed
__device__ unsigned g_wq_hi[(size_t)DIM * THC];            // 3 MB
__device__ unsigned g_mp  [(size_t)BB * NN * HIDDEN];      // 16 MB  mid packed
__device__ unsigned g_wo_hi[(size_t)HIDDEN * DIM];         // 1 MB

// inv_freq[i] = 10000^(-2i/64) = 10^(-i/8), correctly-rounded fp32
__constant__ float c_invfreq[32] = {
    1.0f,
    0.74989420933245582f, 0.56234132519034907f, 0.42169650342858220f,
    0.31622776601683794f, 0.23713737056616552f, 0.17782794100389228f,
    0.13335214321633240f, 0.1f,
    0.074989420933245582f, 0.056234132519034907f, 0.042169650342858220f,
    0.031622776601683794f, 0.023713737056616552f, 0.017782794100389228f,
    0.013335214321633240f, 0.01f,
    0.0074989420933245582f, 0.0056234132519034907f, 0.0042169650342858220f,
    0.0031622776601683794f, 0.0023713737056616552f, 0.0017782794100389228f,
    0.0013335214321633240f, 0.001f,
    0.00074989420933245582f, 0.00056234132519034907f, 0.00042169650342858220f,
    0.00031622776601683794f, 0.00023713737056616552f, 0.00017782794100389228f,
    0.00013335214321633240f
};

// ---------------- tf32 helpers ----------------
__device__ __forceinline__ unsigned cvt_tf32(float f) {
    unsigned r;
    asm("cvt.rna.tf32.f32 %0, %1;" : "=r"(r) : "f"(f));
    return r;
}

__device__ __forceinline__ void mma_tf32(float c[4],
                                         unsigned a0, unsigned a1,
                                         unsigned a2, unsigned a3,
                                         unsigned b0, unsigned b1) {
    asm volatile(
        "mma.sync.aligned.m16n8k8.row.col.f32.tf32.tf32.f32 "
        "{%0,%1,%2,%3}, {%4,%5,%6,%7}, {%8,%9}, {%0,%1,%2,%3};\n"
        : "+f"(c[0]), "+f"(c[1]), "+f"(c[2]), "+f"(c[3])
        : "r"(a0), "r"(a1), "r"(a2), "r"(a3), "r"(b0), "r"(b1));
}

__device__ __forceinline__ void cp16(void* dst_smem, const void* src_gmem) {
    unsigned s = (unsigned)__cvta_generic_to_shared(dst_smem);
    asm volatile("cp.async.cg.shared.global [%0], [%1], 16;"
                 :: "r"(s), "l"(src_gmem));
}
__device__ __forceinline__ void cp_commit() {
    asm volatile("cp.async.commit_group;");
}
__device__ __forceinline__ void cp_wait1() {
    asm volatile("cp.async.wait_group 1;");
}

// =====================================================================
// Pack kernels (proven): m16n8k8 fragment-major tf32 layout.
// =====================================================================
__global__ __launch_bounds__(256)
void pack_a(const float* __restrict__ src, unsigned* __restrict__ dst, int K)
{
    const int gw   = (blockIdx.x * 256 + threadIdx.x) >> 5;
    const int lane = threadIdx.x & 31;
    const int KB   = K >> 3;
    const int mb   = gw / KB;
    const int kb   = gw - mb * KB;
    const int qg   = lane >> 2, q = lane & 3;
    const float* s = src + (size_t)(mb * 16 + qg) * K + kb * 8 + q;
    uint4 o;
    o.x = cvt_tf32(s[0]);
    o.y = cvt_tf32(s[(size_t)8 * K]);
    o.z = cvt_tf32(s[4]);
    o.w = cvt_tf32(s[(size_t)8 * K + 4]);
    *(uint4*)&dst[(size_t)gw * 128 + lane * 4] = o;
}

__global__ __launch_bounds__(256)
void pack_b(const float* __restrict__ src, unsigned* __restrict__ hi,
            int K, int N)
{
    const int gw   = (blockIdx.x * 256 + threadIdx.x) >> 5;
    const int lane = threadIdx.x & 31;
    const int KB2  = K >> 4;
    const int nb   = gw / KB2;
    const int kb2  = gw - nb * KB2;
    const int qg   = lane >> 2, q = lane & 3;
    const float* s = src + (size_t)(kb2 * 16 + q) * N + nb * 8 + qg;
    uint4 h;
    h.x = cvt_tf32(s[0]);
    h.y = cvt_tf32(s[(size_t)4 * N]);
    h.z = cvt_tf32(s[(size_t)8 * N]);
    h.w = cvt_tf32(s[(size_t)12 * N]);
    *(uint4*)&hi[(size_t)gw * 128 + lane * 4] = h;
}

// =====================================================================
// Packed tensor-core GEMM (proven R13/R15 config): block 128m x 64n,
// 256 threads, K-step 32, 3-stage cp.async pipeline, ONE barrier/iter.
// =====================================================================
#define ABUF 4096
#define BBUF 2048

__global__ __launch_bounds__(256)
void pgemm(const unsigned* __restrict__ Ap, const unsigned* __restrict__ Bh,
           float* __restrict__ C, int M, int Nc, int K)
{
    extern __shared__ unsigned sm[];
    unsigned* As  = sm;
    unsigned* Bhs = sm + 3 * ABUF;

    const int tid  = threadIdx.x;
    const int lane = tid & 31;
    const int w    = tid >> 5;
    const int qg   = lane >> 2;
    const int q    = lane & 3;
    const int m0   = blockIdx.y * 128;
    const int n0   = blockIdx.x * 64;
    const int KB   = K >> 3;
    const int KB2  = K >> 4;
    const int NK   = K >> 5;

    const unsigned* Ag  = Ap + (size_t)(m0 >> 4) * KB * 128;
    const unsigned* Bhg = Bh + (size_t)(n0 >> 3) * KB2 * 128;

    const int cw  = tid >> 5;
    const int lw4 = (tid & 31) * 4;

    auto issue_tile = [&](int it, int p) {
        const unsigned* ga = Ag + ((size_t)cw * KB + it * 4) * 128;
        unsigned* da = As + p * ABUF + cw * 512;
#pragma unroll
        for (int s = 0; s < 4; ++s)
            cp16(da + s * 128 + lw4, ga + s * 128 + lw4);
        const unsigned* gb = Bhg + ((size_t)cw * KB2 + it * 2) * 128;
        unsigned* db = Bhs + p * BBUF + cw * 256;
#pragma unroll
        for (int s = 0; s < 2; ++s)
            cp16(db + s * 128 + lw4, gb + s * 128 + lw4);
        cp_commit();
    };

    float C_[8][4];
#pragma unroll
    for (int nt = 0; nt < 8; ++nt)
#pragma unroll
        for (int j = 0; j < 4; ++j) C_[nt][j] = 0.f;

    issue_tile(0, 0);
    issue_tile(1, 1);
    cp_wait1();
    __syncthreads();

    for (int it = 0; it < NK; ++it) {
        const int p = it % 3;
        const int itn = (it + 2 < NK) ? it + 2 : NK - 1;
        issue_tile(itn, (it + 2) % 3);

        uint4 af[4];
#pragma unroll
        for (int kk = 0; kk < 4; ++kk)
            af[kk] = *(const uint4*)&As[p * ABUF + w * 512 + kk * 128 + lane * 4];
#pragma unroll
        for (int nt = 0; nt < 8; ++nt) {
            const unsigned* bb = &Bhs[p * BBUF + nt * 256 + lane * 4];
            uint4 b0 = *(const uint4*)bb;
            uint4 b1 = *(const uint4*)(bb + 128);
            mma_tf32(C_[nt], af[0].x, af[0].y, af[0].z, af[0].w, b0.x, b0.y);
            mma_tf32(C_[nt], af[1].x, af[1].y, af[1].z, af[1].w, b0.z, b0.w);
            mma_tf32(C_[nt], af[2].x, af[2].y, af[2].z, af[2].w, b1.x, b1.y);
            mma_tf32(C_[nt], af[3].x, af[3].y, af[3].z, af[3].w, b1.z, b1.w);
        }

        cp_wait1();
        __syncthreads();
    }

#pragma unroll
    for (int nt = 0; nt < 8; ++nt) {
        int col = n0 + nt * 8 + 2 * q;
        size_t row = (size_t)(m0 + w * 16 + qg);
        *(float2*)&C[row * Nc + col]       = make_float2(C_[nt][0], C_[nt][1]);
        *(float2*)&C[(row + 8) * Nc + col] = make_float2(C_[nt][2], C_[nt][3]);
    }
}

#define PGEMM_SMEM (4 * (3 * ABUF + 3 * BBUF))       // 73728 B

// =====================================================================
// QKV split + rotary (+ q scale). Q row-major; K/V fragment-packed.
// (unchanged — proven)
// =====================================================================
__global__ __launch_bounds__(256)
void qkv_transform()
{
    const int idx  = blockIdx.x * 256 + threadIdx.x;
    const int pair = idx & 31;
    const int n    = (idx >> 5) & (NN - 1);
    const int bh   = idx >> 16;
    const int b    = bh >> 3;
    const int h    = bh & 7;

    const float* src = g_qkv + (size_t)(b * NN + n) * THC;
    const int col = h * DH + pair * 2;

    float2 qv = *(const float2*)&src[col];
    float2 kv = *(const float2*)&src[HIDDEN + col];
    float2 vv = *(const float2*)&src[2 * HIDDEN + col];

    float fr = (float)n * c_invfreq[pair];
    float sn, cs;
    sincosf(fr, &sn, &cs);

    const float scale = 0.125f;
    float oq0 = (qv.x * cs - qv.y * sn) * scale;
    float oq1 = (qv.y * cs + qv.x * sn) * scale;
    float ok0 = kv.x * cs - kv.y * sn;
    float ok1 = kv.y * cs + kv.x * sn;

    const int d0 = pair * 2;
    const size_t bhbase = (size_t)bh * (NN * DH);

    size_t o = bhbase + (size_t)n * DH + d0;
    g_q[o] = oq0; g_q[o + 1] = oq1;

    {
        const int qgk = n & 7, nbk = n >> 3;
        const int kb2 = d0 >> 4;
        size_t kbase = bhbase + ((size_t)nbk * 4 + kb2) * 128;
        int w0 = ((qgk << 2) | (d0 & 3)) * 4 + ((d0 & 15) >> 2);
        int w1 = ((qgk << 2) | ((d0 + 1) & 3)) * 4 + (((d0 + 1) & 15) >> 2);
        g_kp[kbase + w0] = cvt_tf32(ok0);
        g_kp[kbase + w1] = cvt_tf32(ok1);
    }

    {
        const int qv_ = n & 3, rv = (n & 15) >> 2, kb2v = n >> 4;
        const int nb0 = d0 >> 3, qg0 = d0 & 7;
        size_t vbase = bhbase + ((size_t)nb0 * 128 + kb2v) * 128;
        g_vp[vbase + ((qg0 << 2) | qv_) * 4 + rv]       = cvt_tf32(vv.x);
        g_vp[vbase + (((qg0 + 1) << 2) | qv_) * 4 + rv] = cvt_tf32(vv.y);
    }
}

// =====================================================================
// Fused flash attention, tf32, pre-packed K/V — WIDE warp M-tile.
// grid (NN/128, HEADS, BB), block = 128 threads (4 warps x 32 q rows).
// Each warp owns two m16 fragment groups (g=0,1): same 32 LDS.128 per
// iter now feeds 128 mma (was 64) -> chip crossbar traffic halves.
// 3-stage cp.async pipeline of fragment-ready chunks; ONE barrier/iter.
// ~200 regs/thread @128 thr -> 2 blocks/SM (cross-block latency hiding).
// =====================================================================
#define CHUNK_WORDS 4096
#define ATTN_SMEM (3 * CHUNK_WORDS * 4)   // 49152 B

__global__ __launch_bounds__(128)
void attn_tf32(const float* __restrict__ bias)
{
    extern __shared__ unsigned sm[];

    const int tid  = threadIdx.x;
    const int lane = tid & 31;
    const int w    = tid >> 5;            // warp 0..3
    const int qg   = lane >> 2;
    const int q    = lane & 3;
    const int qblk = blockIdx.x * 128;
    const int h    = blockIdx.y;
    const int b    = blockIdx.z;
    const int bh   = b * HEADS + h;
    const unsigned* Kbh = g_kp + (size_t)bh * (NN * DH);
    const unsigned* Vbh = g_vp + (size_t)bh * (NN * DH);
    const float* biasw = bias + (size_t)h * NN * NN
                              + (size_t)(qblk + w * 32) * NN;

    // copy mapping (128 threads): K = 2048 contiguous words, 16/thread;
    // V = 8 regions of 256 words, 16 threads/region, 16 words/thread.
    const int koff = tid * 16;
    const int vreg = tid >> 4;
    const int voff = (tid & 15) * 16;

    auto issue_chunk = [&](int j, int p) {
        unsigned* dst = sm + p * CHUNK_WORDS;
        const unsigned* sk = Kbh + (size_t)j * 2048 + koff;
#pragma unroll
        for (int s = 0; s < 4; ++s)
            cp16(dst + koff + s * 4, sk + s * 4);
        unsigned* dv = dst + 2048 + vreg * 256 + voff;
        const unsigned* sv = Vbh + ((size_t)vreg * 128 + j * 2) * 128 + voff;
#pragma unroll
        for (int s = 0; s < 4; ++s)
            cp16(dv + s * 4, sv + s * 4);
        cp_commit();
    };

    // ---- Q fragments, register-resident: 2 groups of 16 rows ----
    unsigned qa[2][8][4];
#pragma unroll
    for (int g = 0; g < 2; ++g) {
        const float* Qp = g_q + (size_t)bh * (NN * DH)
                        + (size_t)(qblk + w * 32 + g * 16) * DH;
#pragma unroll
        for (int kc = 0; kc < 8; ++kc) {
            qa[g][kc][0] = cvt_tf32(Qp[(size_t)qg       * DH + kc * 8 + q]);
            qa[g][kc][1] = cvt_tf32(Qp[(size_t)(qg + 8) * DH + kc * 8 + q]);
            qa[g][kc][2] = cvt_tf32(Qp[(size_t)qg       * DH + kc * 8 + q + 4]);
            qa[g][kc][3] = cvt_tf32(Qp[(size_t)(qg + 8) * DH + kc * 8 + q + 4]);
        }
    }

    issue_chunk(0, 0);
    issue_chunk(1, 1);

    // bias chunk 0 -> S
    float S[4][2][4];
#pragma unroll
    for (int t = 0; t < 4; ++t)
#pragma unroll
        for (int g = 0; g < 2; ++g) {
            float2 blo = *(const float2*)
                &biasw[(size_t)(g * 16 + qg)     * NN + t * 8 + 2 * q];
            float2 bhi = *(const float2*)
                &biasw[(size_t)(g * 16 + qg + 8) * NN + t * 8 + 2 * q];
            S[t][g][0] = blo.x; S[t][g][1] = blo.y;
            S[t][g][2] = bhi.x; S[t][g][3] = bhi.y;
        }

    cp_wait1();
    __syncthreads();

    float O[2][8][4];
#pragma unroll
    for (int g = 0; g < 2; ++g)
#pragma unroll
        for (int n = 0; n < 8; ++n)
#pragma unroll
            for (int j = 0; j < 4; ++j) O[g][n][j] = 0.f;
    float m_[2][2], l_[2][2];
#pragma unroll
    for (int g = 0; g < 2; ++g) {
        m_[g][0] = -INFINITY; m_[g][1] = -INFINITY;
        l_[g][0] = 0.f;       l_[g][1] = 0.f;
    }

    const int srcA = (lane & ~3) | (q >> 1);
    const int srcB = srcA | 2;

    for (int j = 0; j < 64; ++j) {
        const int p = j % 3;
        issue_chunk((j + 2 < 64) ? j + 2 : 63, (j + 2) % 3);

        // ---- S += Q K^T (16 K LDS.128 feed 64 mma) ----
        const unsigned* KF = sm + p * CHUNK_WORDS;
#pragma unroll
        for (int t = 0; t < 4; ++t) {
            uint4 k0 = *(const uint4*)&KF[t * 512 +   0 + lane * 4];
            uint4 k1 = *(const uint4*)&KF[t * 512 + 128 + lane * 4];
            uint4 k2 = *(const uint4*)&KF[t * 512 + 256 + lane * 4];
            uint4 k3 = *(const uint4*)&KF[t * 512 + 384 + lane * 4];
#pragma unroll
            for (int g = 0; g < 2; ++g) {
                mma_tf32(S[t][g], qa[g][0][0], qa[g][0][1], qa[g][0][2], qa[g][0][3], k0.x, k0.y);
                mma_tf32(S[t][g], qa[g][1][0], qa[g][1][1], qa[g][1][2], qa[g][1][3], k0.z, k0.w);
                mma_tf32(S[t][g], qa[g][2][0], qa[g][2][1], qa[g][2][2], qa[g][2][3], k1.x, k1.y);
                mma_tf32(S[t][g], qa[g][3][0], qa[g][3][1], qa[g][3][2], qa[g][3][3], k1.z, k1.w);
                mma_tf32(S[t][g], qa[g][4][0], qa[g][4][1], qa[g][4][2], qa[g][4][3], k2.x, k2.y);
                mma_tf32(S[t][g], qa[g][5][0], qa[g][5][1], qa[g][5][2], qa[g][5][3], k2.z, k2.w);
                mma_tf32(S[t][g], qa[g][6][0], qa[g][6][1], qa[g][6][2], qa[g][6][3], k3.x, k3.y);
                mma_tf32(S[t][g], qa[g][7][0], qa[g][7][1], qa[g][7][2], qa[g][7][3], k3.z, k3.w);
            }
        }

        // ---- online softmax (per group) ----
#pragma unroll
        for (int g = 0; g < 2; ++g) {
            float cm0 = -INFINITY, cm1 = -INFINITY;
#pragma unroll
            for (int t = 0; t < 4; ++t) {
                cm0 = fmaxf(cm0, fmaxf(S[t][g][0], S[t][g][1]));
                cm1 = fmaxf(cm1, fmaxf(S[t][g][2], S[t][g][3]));
            }
            cm0 = fmaxf(cm0, __shfl_xor_sync(0xffffffffu, cm0, 1));
            cm0 = fmaxf(cm0, __shfl_xor_sync(0xffffffffu, cm0, 2));
            cm1 = fmaxf(cm1, __shfl_xor_sync(0xffffffffu, cm1, 1));
            cm1 = fmaxf(cm1, __shfl_xor_sync(0xffffffffu, cm1, 2));

            float mn0 = fmaxf(m_[g][0], cm0), mn1 = fmaxf(m_[g][1], cm1);
            float al0 = __expf(m_[g][0] - mn0), al1 = __expf(m_[g][1] - mn1);
            m_[g][0] = mn0; m_[g][1] = mn1;

            float s0 = 0.f, s1 = 0.f;
#pragma unroll
            for (int t = 0; t < 4; ++t) {
                S[t][g][0] = __expf(S[t][g][0] - mn0);
                S[t][g][1] = __expf(S[t][g][1] - mn0);
                S[t][g][2] = __expf(S[t][g][2] - mn1);
                S[t][g][3] = __expf(S[t][g][3] - mn1);
                s0 += S[t][g][0] + S[t][g][1];
                s1 += S[t][g][2] + S[t][g][3];
            }
            s0 += __shfl_xor_sync(0xffffffffu, s0, 1);
            s0 += __shfl_xor_sync(0xffffffffu, s0, 2);
            s1 += __shfl_xor_sync(0xffffffffu, s1, 1);
            s1 += __shfl_xor_sync(0xffffffffu, s1, 2);
            l_[g][0] = l_[g][0] * al0 + s0;
            l_[g][1] = l_[g][1] * al1 + s1;
#pragma unroll
            for (int n = 0; n < 8; ++n) {
                O[g][n][0] *= al0; O[g][n][1] *= al0;
                O[g][n][2] *= al1; O[g][n][3] *= al1;
            }
        }

        // ---- P fragments via quad shuffles (both groups) ----
        unsigned pf[4][2][4];
#pragma unroll
        for (int t = 0; t < 4; ++t)
#pragma unroll
            for (int g = 0; g < 2; ++g) {
                unsigned p0 = cvt_tf32(S[t][g][0]);
                unsigned p1 = cvt_tf32(S[t][g][1]);
                unsigned p2 = cvt_tf32(S[t][g][2]);
                unsigned p3 = cvt_tf32(S[t][g][3]);
                unsigned u0 = __shfl_sync(0xffffffffu, p0, srcA);
                unsigned u1 = __shfl_sync(0xffffffffu, p1, srcA);
                unsigned v0 = __shfl_sync(0xffffffffu, p0, srcB);
                unsigned v1 = __shfl_sync(0xffffffffu, p1, srcB);
                unsigned w0 = __shfl_sync(0xffffffffu, p2, srcA);
                unsigned w1 = __shfl_sync(0xffffffffu, p3, srcA);
                unsigned x0 = __shfl_sync(0xffffffffu, p2, srcB);
                unsigned x1 = __shfl_sync(0xffffffffu, p3, srcB);
                pf[t][g][0] = (q & 1) ? u1 : u0;
                pf[t][g][1] = (q & 1) ? w1 : w0;
                pf[t][g][2] = (q & 1) ? v1 : v0;
                pf[t][g][3] = (q & 1) ? x1 : x0;
            }

        // ---- O += P @ V (16 V LDS.128 feed 64 mma) ----
        const unsigned* VF = sm + p * CHUNK_WORDS + 2048;
#pragma unroll
        for (int nt = 0; nt < 8; ++nt) {
            uint4 v0 = *(const uint4*)&VF[nt * 256 +   0 + lane * 4];
            uint4 v1 = *(const uint4*)&VF[nt * 256 + 128 + lane * 4];
#pragma unroll
            for (int g = 0; g < 2; ++g) {
                mma_tf32(O[g][nt], pf[0][g][0], pf[0][g][1], pf[0][g][2], pf[0][g][3], v0.x, v0.y);
                mma_tf32(O[g][nt], pf[1][g][0], pf[1][g][1], pf[1][g][2], pf[1][g][3], v0.z, v0.w);
                mma_tf32(O[g][nt], pf[2][g][0], pf[2][g][1], pf[2][g][2], pf[2][g][3], v1.x, v1.y);
                mma_tf32(O[g][nt], pf[3][g][0], pf[3][g][1], pf[3][g][2], pf[3][g][3], v1.z, v1.w);
            }
        }

        // ---- bias chunk j+1 -> S ----
        {
            const int j0n = ((j + 1 < 64) ? j + 1 : 63) * 32;
#pragma unroll
            for (int t = 0; t < 4; ++t)
#pragma unroll
                for (int g = 0; g < 2; ++g) {
                    float2 blo = *(const float2*)
                        &biasw[(size_t)(g * 16 + qg)     * NN + j0n + t * 8 + 2 * q];
                    float2 bhi = *(const float2*)
                        &biasw[(size_t)(g * 16 + qg + 8) * NN + j0n + t * 8 + 2 * q];
                    S[t][g][0] = blo.x; S[t][g][1] = blo.y;
                    S[t][g][2] = bhi.x; S[t][g][3] = bhi.y;
                }
        }

        cp_wait1();
        __syncthreads();
    }

    // ---- epilogue: /l, refragment to pack_a layout, write g_mp ----
#pragma unroll
    for (int g = 0; g < 2; ++g) {
        const float il0 = 1.f / l_[g][0], il1 = 1.f / l_[g][1];
        const int mb = (b * NN + qblk + w * 32 + g * 16) >> 4;
#pragma unroll
        for (int nt = 0; nt < 8; ++nt) {
            unsigned f0 = __float_as_uint(O[g][nt][0] * il0);
            unsigned f1 = __float_as_uint(O[g][nt][1] * il0);
            unsigned f2 = __float_as_uint(O[g][nt][2] * il1);
            unsigned f3 = __float_as_uint(O[g][nt][3] * il1);
            unsigned u0 = __shfl_sync(0xffffffffu, f0, srcA);
            unsigned u1 = __shfl_sync(0xffffffffu, f1, srcA);
            unsigned w0 = __shfl_sync(0xffffffffu, f2, srcA);
            unsigned w1 = __shfl_sync(0xffffffffu, f3, srcA);
            unsigned x0 = __shfl_sync(0xffffffffu, f0, srcB);
            unsigned x1 = __shfl_sync(0xffffffffu, f1, srcB);
            unsigned y0 = __shfl_sync(0xffffffffu, f2, srcB);
            unsigned y1 = __shfl_sync(0xffffffffu, f3, srcB);
            uint4 o;
            o.x = cvt_tf32(__uint_as_float((q & 1) ? u1 : u0));
            o.y = cvt_tf32(__uint_as_float((q & 1) ? w1 : w0));
            o.z = cvt_tf32(__uint_as_float((q & 1) ? x1 : x0));
            o.w = cvt_tf32(__uint_as_float((q & 1) ? y1 : y0));
            const int kb = h * 8 + nt;
            *(uint4*)&g_mp[((size_t)mb * (HIDDEN / 8) + kb) * 128 + lane * 4] = o;
        }
    }
}

// =====================================================================
extern "C" void kernel_launch(void* const* d_in, const int* in_sizes, int n_in,
                              void* d_out, int out_size)
{
    const float *x = nullptr, *bias = nullptr, *wqkv = nullptr, *wout = nullptr;
    for (int i = 0; i < n_in; ++i) {
        switch (in_sizes[i]) {
            case 4194304:  x    = (const float*)d_in[i]; break;  // x [4,2048,512]
            case 33554432: bias = (const float*)d_in[i]; break;  // pos_bias [8,2048,2048]
            case 786432:   wqkv = (const float*)d_in[i]; break;  // W_qkv [512,1536]
            case 262144:   wout = (const float*)d_in[i]; break;  // W_out [512,512]
        }
    }

    void *p_qkv = nullptr;
    void *p_xp = nullptr, *p_wqh = nullptr;
    void *p_mp = nullptr, *p_woh = nullptr;
    cudaGetSymbolAddress(&p_qkv, g_qkv);
    cudaGetSymbolAddress(&p_xp,  g_xp);
    cudaGetSymbolAddress(&p_wqh, g_wq_hi);
    cudaGetSymbolAddress(&p_mp,  g_mp);
    cudaGetSymbolAddress(&p_woh, g_wo_hi);

    // opt-in to >48KB dynamic smem (non-stream calls: capture-safe)
    cudaFuncSetAttribute(attn_tf32,
                         cudaFuncAttributeMaxDynamicSharedMemorySize,
                         ATTN_SMEM);
    cudaFuncSetAttribute(pgemm,
                         cudaFuncAttributeMaxDynamicSharedMemorySize,
                         PGEMM_SMEM);

    const int MR = BB * NN;   // 8192 rows

    // 0) pack x and W_qkv (both tf32 hi)
    pack_a<<<(MR / 16) * (DIM / 8) / 8, 256>>>(x, (unsigned*)p_xp, DIM);
    pack_b<<<(THC / 8) * (DIM / 16) / 8, 256>>>(
        wqkv, (unsigned*)p_wqh, DIM, THC);

    // 1) qkv = x_hi @ W_hi (1x tf32)
    pgemm<<<dim3(THC / 64, MR / 128), 256, PGEMM_SMEM>>>(
        (const unsigned*)p_xp, (const unsigned*)p_wqh,
        (float*)p_qkv, MR, THC, DIM);

    // 2) split + rotary + scale; K/V written fragment-major packed
    qkv_transform<<<(BB * HEADS * NN * 32) / 256, 256>>>();

    // 3) fused flash attention (wide warp M-tile); writes packed mid
    attn_tf32<<<dim3(NN / 128, HEADS, BB), 128, ATTN_SMEM>>>(bias);

    // 4) out = mid_hi @ Wout_hi (1x tf32)
    pack_b<<<(DIM / 8) * (HIDDEN / 16) / 8, 256>>>(
        wout, (unsigned*)p_woh, HIDDEN, DIM);
    pgemm<<<dim3(DIM / 64, MR / 128), 256, PGEMM_SMEM>>>(
        (const unsigned*)p_mp, (const unsigned*)p_woh,
        (float*)d_out, MR, DIM, HIDDEN);
}

// round 17
// speedup vs baseline: 1.0438x; 1.0438x over previous
#include <cuda_runtime.h>
#include <math.h>

// Problem constants
#define BB 4
#define NN 2048
#define DIM 512
#define HEADS 8
#define DH 64
#define HIDDEN 512          // HEADS*DH
#define THC 1536            // 3*HIDDEN

// ---------------- scratch (device globals: allocation-free rule) ----------
__device__ float    g_q  [(size_t)BB * HEADS * NN * DH];   // 16 MB
// fragment-major packed operands (tf32 bit patterns)
__device__ unsigned g_kp  [(size_t)BB * HEADS * NN * DH];  // 16 MB  K packed
__device__ unsigned g_vp  [(size_t)BB * HEADS * NN * DH];  // 16 MB  V packed
__device__ unsigned g_xp  [(size_t)BB * NN * DIM];         // 16 MB  x packed
__device__ unsigned g_wq_hi[(size_t)DIM * THC];            // 3 MB
__device__ unsigned g_mp  [(size_t)BB * NN * HIDDEN];      // 16 MB  mid packed
__device__ unsigned g_wo_hi[(size_t)HIDDEN * DIM];         // 1 MB

// inv_freq[i] = 10000^(-2i/64) = 10^(-i/8), correctly-rounded fp32
__constant__ float c_invfreq[32] = {
    1.0f,
    0.74989420933245582f, 0.56234132519034907f, 0.42169650342858220f,
    0.31622776601683794f, 0.23713737056616552f, 0.17782794100389228f,
    0.13335214321633240f, 0.1f,
    0.074989420933245582f, 0.056234132519034907f, 0.042169650342858220f,
    0.031622776601683794f, 0.023713737056616552f, 0.017782794100389228f,
    0.013335214321633240f, 0.01f,
    0.0074989420933245582f, 0.0056234132519034907f, 0.0042169650342858220f,
    0.0031622776601683794f, 0.0023713737056616552f, 0.0017782794100389228f,
    0.0013335214321633240f, 0.001f,
    0.00074989420933245582f, 0.00056234132519034907f, 0.00042169650342858220f,
    0.00031622776601683794f, 0.00023713737056616552f, 0.00017782794100389228f,
    0.00013335214321633240f
};

// ---------------- tf32 helpers ----------------
__device__ __forceinline__ unsigned cvt_tf32(float f) {
    unsigned r;
    asm("cvt.rna.tf32.f32 %0, %1;" : "=r"(r) : "f"(f));
    return r;
}

__device__ __forceinline__ void mma_tf32(float c[4],
                                         unsigned a0, unsigned a1,
                                         unsigned a2, unsigned a3,
                                         unsigned b0, unsigned b1) {
    asm volatile(
        "mma.sync.aligned.m16n8k8.row.col.f32.tf32.tf32.f32 "
        "{%0,%1,%2,%3}, {%4,%5,%6,%7}, {%8,%9}, {%0,%1,%2,%3};\n"
        : "+f"(c[0]), "+f"(c[1]), "+f"(c[2]), "+f"(c[3])
        : "r"(a0), "r"(a1), "r"(a2), "r"(a3), "r"(b0), "r"(b1));
}

__device__ __forceinline__ void cp16(void* dst_smem, const void* src_gmem) {
    unsigned s = (unsigned)__cvta_generic_to_shared(dst_smem);
    asm volatile("cp.async.cg.shared.global [%0], [%1], 16;"
                 :: "r"(s), "l"(src_gmem));
}
__device__ __forceinline__ void cp_commit() {
    asm volatile("cp.async.commit_group;");
}
__device__ __forceinline__ void cp_wait1() {
    asm volatile("cp.async.wait_group 1;");
}

// =====================================================================
// Pack kernels (proven): m16n8k8 fragment-major tf32 layout.
// =====================================================================
__global__ __launch_bounds__(256)
void pack_a(const float* __restrict__ src, unsigned* __restrict__ dst, int K)
{
    const int gw   = (blockIdx.x * 256 + threadIdx.x) >> 5;
    const int lane = threadIdx.x & 31;
    const int KB   = K >> 3;
    const int mb   = gw / KB;
    const int kb   = gw - mb * KB;
    const int qg   = lane >> 2, q = lane & 3;
    const float* s = src + (size_t)(mb * 16 + qg) * K + kb * 8 + q;
    uint4 o;
    o.x = cvt_tf32(s[0]);
    o.y = cvt_tf32(s[(size_t)8 * K]);
    o.z = cvt_tf32(s[4]);
    o.w = cvt_tf32(s[(size_t)8 * K + 4]);
    *(uint4*)&dst[(size_t)gw * 128 + lane * 4] = o;
}

__global__ __launch_bounds__(256)
void pack_b(const float* __restrict__ src, unsigned* __restrict__ hi,
            int K, int N)
{
    const int gw   = (blockIdx.x * 256 + threadIdx.x) >> 5;
    const int lane = threadIdx.x & 31;
    const int KB2  = K >> 4;
    const int nb   = gw / KB2;
    const int kb2  = gw - nb * KB2;
    const int qg   = lane >> 2, q = lane & 3;
    const float* s = src + (size_t)(kb2 * 16 + q) * N + nb * 8 + qg;
    uint4 h;
    h.x = cvt_tf32(s[0]);
    h.y = cvt_tf32(s[(size_t)4 * N]);
    h.z = cvt_tf32(s[(size_t)8 * N]);
    h.w = cvt_tf32(s[(size_t)12 * N]);
    *(uint4*)&hi[(size_t)gw * 128 + lane * 4] = h;
}

// =====================================================================
// Packed tensor-core GEMM (proven R13/R15 mainloop): block 128m x 64n,
// 256 threads, K-step 32, 3-stage cp.async pipeline, ONE barrier/iter.
// EPI=0: plain fp32 C store.
// EPI=1: fused QKV epilogue — the 64-col block lies wholly in Q, K or V
//   (64 | 512, block-uniform). Q: rotary+scale -> g_q row-major.
//   K: rotary -> g_kp packed. V: -> g_vp packed. Mappings verbatim from
//   the proven qkv_transform; values bit-identical (replaced fp32
//   store/load round-trip is exact).
// =====================================================================
#define ABUF 4096
#define BBUF 2048

template<int EPI>
__global__ __launch_bounds__(256)
void pgemm(const unsigned* __restrict__ Ap, const unsigned* __restrict__ Bh,
           float* __restrict__ C, int M, int Nc, int K)
{
    extern __shared__ unsigned sm[];
    unsigned* As  = sm;
    unsigned* Bhs = sm + 3 * ABUF;

    const int tid  = threadIdx.x;
    const int lane = tid & 31;
    const int w    = tid >> 5;
    const int qg   = lane >> 2;
    const int q    = lane & 3;
    const int m0   = blockIdx.y * 128;
    const int n0   = blockIdx.x * 64;
    const int KB   = K >> 3;
    const int KB2  = K >> 4;
    const int NK   = K >> 5;

    const unsigned* Ag  = Ap + (size_t)(m0 >> 4) * KB * 128;
    const unsigned* Bhg = Bh + (size_t)(n0 >> 3) * KB2 * 128;

    const int cw  = tid >> 5;
    const int lw4 = (tid & 31) * 4;

    auto issue_tile = [&](int it, int p) {
        const unsigned* ga = Ag + ((size_t)cw * KB + it * 4) * 128;
        unsigned* da = As + p * ABUF + cw * 512;
#pragma unroll
        for (int s = 0; s < 4; ++s)
            cp16(da + s * 128 + lw4, ga + s * 128 + lw4);
        const unsigned* gb = Bhg + ((size_t)cw * KB2 + it * 2) * 128;
        unsigned* db = Bhs + p * BBUF + cw * 256;
#pragma unroll
        for (int s = 0; s < 2; ++s)
            cp16(db + s * 128 + lw4, gb + s * 128 + lw4);
        cp_commit();
    };

    float C_[8][4];
#pragma unroll
    for (int nt = 0; nt < 8; ++nt)
#pragma unroll
        for (int j = 0; j < 4; ++j) C_[nt][j] = 0.f;

    issue_tile(0, 0);
    issue_tile(1, 1);
    cp_wait1();
    __syncthreads();

    for (int it = 0; it < NK; ++it) {
        const int p = it % 3;
        const int itn = (it + 2 < NK) ? it + 2 : NK - 1;
        issue_tile(itn, (it + 2) % 3);

        uint4 af[4];
#pragma unroll
        for (int kk = 0; kk < 4; ++kk)
            af[kk] = *(const uint4*)&As[p * ABUF + w * 512 + kk * 128 + lane * 4];
#pragma unroll
        for (int nt = 0; nt < 8; ++nt) {
            const unsigned* bb = &Bhs[p * BBUF + nt * 256 + lane * 4];
            uint4 b0 = *(const uint4*)bb;
            uint4 b1 = *(const uint4*)(bb + 128);
            mma_tf32(C_[nt], af[0].x, af[0].y, af[0].z, af[0].w, b0.x, b0.y);
            mma_tf32(C_[nt], af[1].x, af[1].y, af[1].z, af[1].w, b0.z, b0.w);
            mma_tf32(C_[nt], af[2].x, af[2].y, af[2].z, af[2].w, b1.x, b1.y);
            mma_tf32(C_[nt], af[3].x, af[3].y, af[3].z, af[3].w, b1.z, b1.w);
        }

        cp_wait1();
        __syncthreads();
    }

    if (EPI == 0) {
#pragma unroll
        for (int nt = 0; nt < 8; ++nt) {
            int col = n0 + nt * 8 + 2 * q;
            size_t row = (size_t)(m0 + w * 16 + qg);
            *(float2*)&C[row * Nc + col]       = make_float2(C_[nt][0], C_[nt][1]);
            *(float2*)&C[(row + 8) * Nc + col] = make_float2(C_[nt][2], C_[nt][3]);
        }
    } else {
        // ---- fused QKV epilogue: rotary/split/pack ----
        const int sec = n0 >> 9;            // 0=Q, 1=K, 2=V (block-uniform)
#pragma unroll
        for (int nt = 0; nt < 8; ++nt) {
            const int c      = n0 + nt * 8 + 2 * q;
            const int within = c & 511;
            const int hh     = within >> 6;
            const int d0     = within & 63;       // even
#pragma unroll
            for (int rr = 0; rr < 2; ++rr) {
                const int grow = m0 + w * 16 + qg + rr * 8;
                const int b_   = grow >> 11;
                const int n_   = grow & (NN - 1);
                const float v0 = C_[nt][rr * 2 + 0];
                const float v1 = C_[nt][rr * 2 + 1];
                const size_t bhbase = (size_t)(b_ * HEADS + hh) * (NN * DH);
                if (sec == 0) {
                    float sn, cs;
                    sincosf((float)n_ * c_invfreq[d0 >> 1], &sn, &cs);
                    float o0 = (v0 * cs - v1 * sn) * 0.125f;
                    float o1 = (v1 * cs + v0 * sn) * 0.125f;
                    *(float2*)&g_q[bhbase + (size_t)n_ * DH + d0] =
                        make_float2(o0, o1);
                } else if (sec == 1) {
                    float sn, cs;
                    sincosf((float)n_ * c_invfreq[d0 >> 1], &sn, &cs);
                    float o0 = v0 * cs - v1 * sn;
                    float o1 = v1 * cs + v0 * sn;
                    const int qgk = n_ & 7, nbk = n_ >> 3, kb2 = d0 >> 4;
                    size_t kbase = bhbase + ((size_t)nbk * 4 + kb2) * 128;
                    int w0 = ((qgk << 2) | (d0 & 3)) * 4 + ((d0 & 15) >> 2);
                    int w1 = ((qgk << 2) | ((d0 + 1) & 3)) * 4
                           + (((d0 + 1) & 15) >> 2);
                    g_kp[kbase + w0] = cvt_tf32(o0);
                    g_kp[kbase + w1] = cvt_tf32(o1);
                } else {
                    const int qv_ = n_ & 3, rv = (n_ & 15) >> 2, kb2v = n_ >> 4;
                    const int nb0 = d0 >> 3, qg0 = d0 & 7;
                    size_t vbase = bhbase + ((size_t)nb0 * 128 + kb2v) * 128;
                    g_vp[vbase + ((qg0 << 2) | qv_) * 4 + rv]       = cvt_tf32(v0);
                    g_vp[vbase + (((qg0 + 1) << 2) | qv_) * 4 + rv] = cvt_tf32(v1);
                }
            }
        }
    }
}

#define PGEMM_SMEM (4 * (3 * ABUF + 3 * BBUF))       // 73728 B

// =====================================================================
// Fused flash attention, tf32, pre-packed K/V (R15 proven version).
// grid (NN/128, HEADS, BB), block 256 (8 warps x 16 q rows), chunk 32.
// =====================================================================
#define CHUNK_WORDS 4096
#define ATTN_SMEM (3 * CHUNK_WORDS * 4)   // 49152 B

__global__ __launch_bounds__(256, 2)
void attn_tf32(const float* __restrict__ bias)
{
    extern __shared__ unsigned sm[];

    const int tid  = threadIdx.x;
    const int lane = tid & 31;
    const int w    = tid >> 5;
    const int qg   = lane >> 2;
    const int q    = lane & 3;
    const int qblk = blockIdx.x * 128;
    const int h    = blockIdx.y;
    const int b    = blockIdx.z;
    const int bh   = b * HEADS + h;
    const unsigned* Kbh = g_kp + (size_t)bh * (NN * DH);
    const unsigned* Vbh = g_vp + (size_t)bh * (NN * DH);
    const float* biasw = bias + (size_t)h * NN * NN
                              + (size_t)(qblk + w * 16) * NN;

    const int koff = tid * 8;
    const int vreg = tid >> 5;
    const int voff = (tid & 31) * 8;

    auto issue_chunk = [&](int j, int p) {
        unsigned* dst = sm + p * CHUNK_WORDS;
        const unsigned* sk = Kbh + (size_t)j * 2048 + koff;
        cp16(dst + koff,     sk);
        cp16(dst + koff + 4, sk + 4);
        unsigned* dv = dst + 2048 + vreg * 256 + voff;
        const unsigned* sv = Vbh + ((size_t)vreg * 128 + j * 2) * 128 + voff;
        cp16(dv,     sv);
        cp16(dv + 4, sv + 4);
        cp_commit();
    };

    unsigned qa[8][4];
    {
        const float* Qp = g_q + (size_t)bh * (NN * DH)
                        + (size_t)(qblk + w * 16) * DH;
#pragma unroll
        for (int kc = 0; kc < 8; ++kc) {
            qa[kc][0] = cvt_tf32(Qp[(size_t)qg       * DH + kc * 8 + q]);
            qa[kc][1] = cvt_tf32(Qp[(size_t)(qg + 8) * DH + kc * 8 + q]);
            qa[kc][2] = cvt_tf32(Qp[(size_t)qg       * DH + kc * 8 + q + 4]);
            qa[kc][3] = cvt_tf32(Qp[(size_t)(qg + 8) * DH + kc * 8 + q + 4]);
        }
    }

    issue_chunk(0, 0);
    issue_chunk(1, 1);

    float S[4][4];
#pragma unroll
    for (int t = 0; t < 4; ++t) {
        float2 blo = *(const float2*)&biasw[(size_t)qg       * NN + t * 8 + 2 * q];
        float2 bhi = *(const float2*)&biasw[(size_t)(qg + 8) * NN + t * 8 + 2 * q];
        S[t][0] = blo.x; S[t][1] = blo.y;
        S[t][2] = bhi.x; S[t][3] = bhi.y;
    }

    cp_wait1();
    __syncthreads();

    float O[8][4];
#pragma unroll
    for (int n = 0; n < 8; ++n)
#pragma unroll
        for (int j = 0; j < 4; ++j) O[n][j] = 0.f;
    float m0 = -INFINITY, m1 = -INFINITY, l0 = 0.f, l1 = 0.f;

    const int srcA = (lane & ~3) | (q >> 1);
    const int srcB = srcA | 2;

    for (int j = 0; j < 64; ++j) {
        const int p = j % 3;
        issue_chunk((j + 2 < 64) ? j + 2 : 63, (j + 2) % 3);

        const unsigned* KF = sm + p * CHUNK_WORDS;
#pragma unroll
        for (int t = 0; t < 4; ++t) {
            uint4 k0 = *(const uint4*)&KF[t * 512 +   0 + lane * 4];
            uint4 k1 = *(const uint4*)&KF[t * 512 + 128 + lane * 4];
            uint4 k2 = *(const uint4*)&KF[t * 512 + 256 + lane * 4];
            uint4 k3 = *(const uint4*)&KF[t * 512 + 384 + lane * 4];
            mma_tf32(S[t], qa[0][0], qa[0][1], qa[0][2], qa[0][3], k0.x, k0.y);
            mma_tf32(S[t], qa[1][0], qa[1][1], qa[1][2], qa[1][3], k0.z, k0.w);
            mma_tf32(S[t], qa[2][0], qa[2][1], qa[2][2], qa[2][3], k1.x, k1.y);
            mma_tf32(S[t], qa[3][0], qa[3][1], qa[3][2], qa[3][3], k1.z, k1.w);
            mma_tf32(S[t], qa[4][0], qa[4][1], qa[4][2], qa[4][3], k2.x, k2.y);
            mma_tf32(S[t], qa[5][0], qa[5][1], qa[5][2], qa[5][3], k2.z, k2.w);
            mma_tf32(S[t], qa[6][0], qa[6][1], qa[6][2], qa[6][3], k3.x, k3.y);
            mma_tf32(S[t], qa[7][0], qa[7][1], qa[7][2], qa[7][3], k3.z, k3.w);
        }

        float cm0 = -INFINITY, cm1 = -INFINITY;
#pragma unroll
        for (int t = 0; t < 4; ++t) {
            cm0 = fmaxf(cm0, fmaxf(S[t][0], S[t][1]));
            cm1 = fmaxf(cm1, fmaxf(S[t][2], S[t][3]));
        }
        cm0 = fmaxf(cm0, __shfl_xor_sync(0xffffffffu, cm0, 1));
        cm0 = fmaxf(cm0, __shfl_xor_sync(0xffffffffu, cm0, 2));
        cm1 = fmaxf(cm1, __shfl_xor_sync(0xffffffffu, cm1, 1));
        cm1 = fmaxf(cm1, __shfl_xor_sync(0xffffffffu, cm1, 2));

        float mn0 = fmaxf(m0, cm0), mn1 = fmaxf(m1, cm1);
        float al0 = __expf(m0 - mn0), al1 = __expf(m1 - mn1);
        m0 = mn0; m1 = mn1;

        float s0 = 0.f, s1 = 0.f;
#pragma unroll
        for (int t = 0; t < 4; ++t) {
            S[t][0] = __expf(S[t][0] - mn0);
            S[t][1] = __expf(S[t][1] - mn0);
            S[t][2] = __expf(S[t][2] - mn1);
            S[t][3] = __expf(S[t][3] - mn1);
            s0 += S[t][0] + S[t][1];
            s1 += S[t][2] + S[t][3];
        }
        s0 += __shfl_xor_sync(0xffffffffu, s0, 1);
        s0 += __shfl_xor_sync(0xffffffffu, s0, 2);
        s1 += __shfl_xor_sync(0xffffffffu, s1, 1);
        s1 += __shfl_xor_sync(0xffffffffu, s1, 2);
        l0 = l0 * al0 + s0;
        l1 = l1 * al1 + s1;
#pragma unroll
        for (int n = 0; n < 8; ++n) {
            O[n][0] *= al0; O[n][1] *= al0;
            O[n][2] *= al1; O[n][3] *= al1;
        }

        unsigned pf[4][4];
#pragma unroll
        for (int t = 0; t < 4; ++t) {
            unsigned p0 = cvt_tf32(S[t][0]);
            unsigned p1 = cvt_tf32(S[t][1]);
            unsigned p2 = cvt_tf32(S[t][2]);
            unsigned p3 = cvt_tf32(S[t][3]);
            unsigned u0 = __shfl_sync(0xffffffffu, p0, srcA);
            unsigned u1 = __shfl_sync(0xffffffffu, p1, srcA);
            unsigned v0 = __shfl_sync(0xffffffffu, p0, srcB);
            unsigned v1 = __shfl_sync(0xffffffffu, p1, srcB);
            unsigned w0 = __shfl_sync(0xffffffffu, p2, srcA);
            unsigned w1 = __shfl_sync(0xffffffffu, p3, srcA);
            unsigned x0 = __shfl_sync(0xffffffffu, p2, srcB);
            unsigned x1 = __shfl_sync(0xffffffffu, p3, srcB);
            pf[t][0] = (q & 1) ? u1 : u0;
            pf[t][1] = (q & 1) ? w1 : w0;
            pf[t][2] = (q & 1) ? v1 : v0;
            pf[t][3] = (q & 1) ? x1 : x0;
        }

        const unsigned* VF = sm + p * CHUNK_WORDS + 2048;
#pragma unroll
        for (int nt = 0; nt < 8; ++nt) {
            uint4 v0 = *(const uint4*)&VF[nt * 256 +   0 + lane * 4];
            uint4 v1 = *(const uint4*)&VF[nt * 256 + 128 + lane * 4];
            mma_tf32(O[nt], pf[0][0], pf[0][1], pf[0][2], pf[0][3], v0.x, v0.y);
            mma_tf32(O[nt], pf[1][0], pf[1][1], pf[1][2], pf[1][3], v0.z, v0.w);
            mma_tf32(O[nt], pf[2][0], pf[2][1], pf[2][2], pf[2][3], v1.x, v1.y);
            mma_tf32(O[nt], pf[3][0], pf[3][1], pf[3][2], pf[3][3], v1.z, v1.w);
        }

        {
            const int j0n = ((j + 1 < 64) ? j + 1 : 63) * 32;
#pragma unroll
            for (int t = 0; t < 4; ++t) {
                float2 blo = *(const float2*)
                    &biasw[(size_t)qg       * NN + j0n + t * 8 + 2 * q];
                float2 bhi = *(const float2*)
                    &biasw[(size_t)(qg + 8) * NN + j0n + t * 8 + 2 * q];
                S[t][0] = blo.x; S[t][1] = blo.y;
                S[t][2] = bhi.x; S[t][3] = bhi.y;
            }
        }

        cp_wait1();
        __syncthreads();
    }

    const float il0 = 1.f / l0, il1 = 1.f / l1;
    const int mb = (b * NN + qblk + w * 16) >> 4;
#pragma unroll
    for (int nt = 0; nt < 8; ++nt) {
        unsigned f0 = __float_as_uint(O[nt][0] * il0);
        unsigned f1 = __float_as_uint(O[nt][1] * il0);
        unsigned f2 = __float_as_uint(O[nt][2] * il1);
        unsigned f3 = __float_as_uint(O[nt][3] * il1);
        unsigned u0 = __shfl_sync(0xffffffffu, f0, srcA);
        unsigned u1 = __shfl_sync(0xffffffffu, f1, srcA);
        unsigned w0 = __shfl_sync(0xffffffffu, f2, srcA);
        unsigned w1 = __shfl_sync(0xffffffffu, f3, srcA);
        unsigned x0 = __shfl_sync(0xffffffffu, f0, srcB);
        unsigned x1 = __shfl_sync(0xffffffffu, f1, srcB);
        unsigned y0 = __shfl_sync(0xffffffffu, f2, srcB);
        unsigned y1 = __shfl_sync(0xffffffffu, f3, srcB);
        uint4 o;
        o.x = cvt_tf32(__uint_as_float((q & 1) ? u1 : u0));
        o.y = cvt_tf32(__uint_as_float((q & 1) ? w1 : w0));
        o.z = cvt_tf32(__uint_as_float((q & 1) ? x1 : x0));
        o.w = cvt_tf32(__uint_as_float((q & 1) ? y1 : y0));
        const int kb = h * 8 + nt;
        *(uint4*)&g_mp[((size_t)mb * (HIDDEN / 8) + kb) * 128 + lane * 4] = o;
    }
}

// =====================================================================
extern "C" void kernel_launch(void* const* d_in, const int* in_sizes, int n_in,
                              void* d_out, int out_size)
{
    const float *x = nullptr, *bias = nullptr, *wqkv = nullptr, *wout = nullptr;
    for (int i = 0; i < n_in; ++i) {
        switch (in_sizes[i]) {
            case 4194304:  x    = (const float*)d_in[i]; break;  // x [4,2048,512]
            case 33554432: bias = (const float*)d_in[i]; break;  // pos_bias [8,2048,2048]
            case 786432:   wqkv = (const float*)d_in[i]; break;  // W_qkv [512,1536]
            case 262144:   wout = (const float*)d_in[i]; break;  // W_out [512,512]
        }
    }

    void *p_xp = nullptr, *p_wqh = nullptr;
    void *p_mp = nullptr, *p_woh = nullptr;
    cudaGetSymbolAddress(&p_xp,  g_xp);
    cudaGetSymbolAddress(&p_wqh, g_wq_hi);
    cudaGetSymbolAddress(&p_mp,  g_mp);
    cudaGetSymbolAddress(&p_woh, g_wo_hi);

    // opt-in to >48KB dynamic smem (non-stream calls: capture-safe)
    cudaFuncSetAttribute(attn_tf32,
                         cudaFuncAttributeMaxDynamicSharedMemorySize,
                         ATTN_SMEM);
    cudaFuncSetAttribute(pgemm<0>,
                         cudaFuncAttributeMaxDynamicSharedMemorySize,
                         PGEMM_SMEM);
    cudaFuncSetAttribute(pgemm<1>,
                         cudaFuncAttributeMaxDynamicSharedMemorySize,
                         PGEMM_SMEM);

    const int MR = BB * NN;   // 8192 rows

    // 0) pack x and W_qkv (both tf32 hi)
    pack_a<<<(MR / 16) * (DIM / 8) / 8, 256>>>(x, (unsigned*)p_xp, DIM);
    pack_b<<<(THC / 8) * (DIM / 16) / 8, 256>>>(
        wqkv, (unsigned*)p_wqh, DIM, THC);

    // 1) qkv GEMM with FUSED rotary/split/pack epilogue:
    //    Q -> g_q (row-major), K -> g_kp, V -> g_vp (fragment-packed).
    pgemm<1><<<dim3(THC / 64, MR / 128), 256, PGEMM_SMEM>>>(
        (const unsigned*)p_xp, (const unsigned*)p_wqh,
        (float*)nullptr, MR, THC, DIM);

    // 2) fused flash attention (pre-packed K/V); writes packed mid
    attn_tf32<<<dim3(NN / 128, HEADS, BB), 256, ATTN_SMEM>>>(bias);

    // 3) out = mid_hi @ Wout_hi (1x tf32)
    pack_b<<<(DIM / 8) * (HIDDEN / 16) / 8, 256>>>(
        wout, (unsigned*)p_woh, HIDDEN, DIM);
    pgemm<0><<<dim3(DIM / 64, MR / 128), 256, PGEMM_SMEM>>>(
        (const unsigned*)p_mp, (const unsigned*)p_woh,
        (float*)d_out, MR, DIM, HIDDEN);
}